// round 1
// baseline (speedup 1.0000x reference)
#include <cuda_runtime.h>

// ShapeConv: out[b,o] = -2 * ( max_t( conv[b,o,t] - win_norm[b,t] ) - w_norm[o] )
// conv[b,o,t] = sum_{c,k} x[b,c,t+k] * w[o,c,k]
// Shapes: x[32,3,8192] f32, w[128,3,64] f32, out[32,128] f32.

#define BB 32
#define CC 3
#define LL 8192
#define OO 128
#define KW 64
#define WW (LL - KW + 1)          /* 8129 valid windows */
#define TT 128                    /* time tile per block */
#define NT ((WW + TT - 1) / TT)   /* 64 tiles */
#define XP 192                    /* x smem pitch (TT + KW - 1 = 191, pad to 192) */

#define W_S_FLOATS (OO * CC * KW)             /* 24576 */
#define SMEM_FLOATS (W_S_FLOATS + CC * XP + XP + TT)
#define SMEM_BYTES (SMEM_FLOATS * 4)          /* 101,888 B */

__device__ unsigned int g_max[BB * OO];

// Monotone float -> uint map (order preserving for all finite floats and infs)
__device__ __forceinline__ unsigned int f2mono(float f) {
    unsigned int u = __float_as_uint(f);
    return (u & 0x80000000u) ? ~u : (u | 0x80000000u);
}
__device__ __forceinline__ float mono2f(unsigned int m) {
    unsigned int u = (m & 0x80000000u) ? (m & 0x7fffffffu) : ~m;
    return __uint_as_float(u);
}

// Packed f32x2 helpers (FFMA2 — rt_SMSP=1, 2x throughput vs 3-reg FFMA)
__device__ __forceinline__ unsigned long long pk2(float a, float b) {
    unsigned long long r;
    asm("mov.b64 %0, {%1,%2};" : "=l"(r) : "f"(a), "f"(b));
    return r;
}
__device__ __forceinline__ void fma2(unsigned long long& d,
                                     unsigned long long a,
                                     unsigned long long b) {
    asm("fma.rn.f32x2 %0, %1, %2, %0;" : "+l"(d) : "l"(a), "l"(b));
}

__global__ void shapeconv_init() {
    int idx = blockIdx.x * blockDim.x + threadIdx.x;
    if (idx < BB * OO) g_max[idx] = 0u;   // 0 < mapped(-inf) = 0x007FFFFF
}

extern "C" __global__ void __launch_bounds__(256, 2)
shapeconv_main(const float* __restrict__ xg, const float* __restrict__ wg) {
    extern __shared__ float smem[];
    float* w_s   = smem;                       // [C*KW][O], w_s[kk*O + o]
    float* x_s   = smem + W_S_FLOATS;          // [C][XP]
    float* sq_s  = x_s + CC * XP;              // [XP]
    float* win_s = sq_s + XP;                  // [TT]

    const int tid = threadIdx.x;
    const int b   = blockIdx.y;
    const int t0b = blockIdx.x * TT;

    // ---- load weights into smem, transposed to [kk][o] ----
    // consecutive tid -> consecutive o (coalesced STS; global strided reads hit L2)
    for (int i = tid; i < W_S_FLOATS; i += 256) {
        int o  = i & (OO - 1);
        int kk = i >> 7;
        w_s[i] = wg[o * (CC * KW) + kk];
    }

    // ---- load x tile (zero-padded past L) + per-position squared sums ----
    const float* xb = xg + b * CC * LL;
    for (int j = tid; j < TT + KW - 1; j += 256) {
        int g = t0b + j;
        float a0 = 0.f, a1 = 0.f, a2 = 0.f;
        if (g < LL) { a0 = xb[g]; a1 = xb[LL + g]; a2 = xb[2 * LL + g]; }
        x_s[j] = a0; x_s[XP + j] = a1; x_s[2 * XP + j] = a2;
        sq_s[j] = a0 * a0 + a1 * a1 + a2 * a2;
    }
    __syncthreads();

    // ---- window half-norms; +inf masks invalid t so they never win the max ----
    if (tid < TT) {
        float s = 0.f;
        #pragma unroll 8
        for (int k = 0; k < KW; ++k) s += sq_s[tid + k];
        win_s[tid] = (t0b + tid < WW) ? 0.5f * s : __int_as_float(0x7f800000);
    }
    __syncthreads();

    // ---- register-tiled implicit GEMM: 8 o x 8 t per thread, o packed in f32x2 ----
    const int tt = tid & 15;       // 16 threads along t
    const int to = tid >> 4;       // 16 threads along o
    const int o0 = to * 8;
    const int t0 = tt * 8;

    unsigned long long acc[4][8];  // acc[i][j]: o-pair (o0+2i, o0+2i+1) at t0+j
    #pragma unroll
    for (int i = 0; i < 4; ++i)
        #pragma unroll
        for (int j = 0; j < 8; ++j) acc[i][j] = 0ull;

    #pragma unroll
    for (int c = 0; c < CC; ++c) {
        const float* xc   = x_s + c * XP + t0;
        const float* wrow = w_s + (c * KW) * OO + o0;

        float xr[8];                       // rotation buffer: xr[(k+j)&7] = x[t0+k+j]
        #pragma unroll
        for (int j = 0; j < 8; ++j) xr[j] = xc[j];

        for (int kb = 0; kb < KW; kb += 8) {
            #pragma unroll
            for (int ku = 0; ku < 8; ++ku) {
                const unsigned long long* wp =
                    (const unsigned long long*)(wrow + (kb + ku) * OO);
                unsigned long long w0 = wp[0], w1 = wp[1], w2 = wp[2], w3 = wp[3];
                #pragma unroll
                for (int j = 0; j < 8; ++j) {
                    float xv = xr[(ku + j) & 7];
                    unsigned long long xpair = pk2(xv, xv);
                    fma2(acc[0][j], w0, xpair);
                    fma2(acc[1][j], w1, xpair);
                    fma2(acc[2][j], w2, xpair);
                    fma2(acc[3][j], w3, xpair);
                }
                xr[ku] = xc[kb + ku + 8];  // refill: x[t0 + k + 8]
            }
        }
    }

    // ---- epilogue: feature = conv - win_norm, max over this thread's 8 t ----
    float mo[8];
    #pragma unroll
    for (int i = 0; i < 8; ++i) mo[i] = __int_as_float(0xff800000);  // -inf
    #pragma unroll
    for (int i = 0; i < 4; ++i) {
        #pragma unroll
        for (int j = 0; j < 8; ++j) {
            float lo, hi;
            asm("mov.b64 {%0,%1}, %2;" : "=f"(lo), "=f"(hi) : "l"(acc[i][j]));
            float wn = win_s[t0 + j];
            mo[2 * i]     = fmaxf(mo[2 * i],     lo - wn);
            mo[2 * i + 1] = fmaxf(mo[2 * i + 1], hi - wn);
        }
    }
    // max across the 16 t-threads (xor 1..8 stays within each 16-lane half-warp)
    #pragma unroll
    for (int i = 0; i < 8; ++i) {
        #pragma unroll
        for (int s = 1; s < 16; s <<= 1)
            mo[i] = fmaxf(mo[i], __shfl_xor_sync(0xffffffffu, mo[i], s));
    }
    if (tt == 0) {
        unsigned int* gm = g_max + b * OO + o0;
        #pragma unroll
        for (int i = 0; i < 8; ++i) atomicMax(gm + i, f2mono(mo[i]));
    }
}

__global__ void shapeconv_finalize(const float* __restrict__ wg,
                                   float* __restrict__ out) {
    int idx = blockIdx.x * blockDim.x + threadIdx.x;
    if (idx >= BB * OO) return;
    int o = idx & (OO - 1);
    const float* wr = wg + o * (CC * KW);
    float s = 0.f;
    #pragma unroll 8
    for (int i = 0; i < CC * KW; ++i) s += wr[i] * wr[i];
    float v = mono2f(g_max[idx]);
    out[idx] = -2.0f * (v - 0.5f * s);
}

extern "C" void kernel_launch(void* const* d_in, const int* in_sizes, int n_in,
                              void* d_out, int out_size) {
    const float* x = (const float*)d_in[0];
    const float* w = (const float*)d_in[1];
    float* out = (float*)d_out;

    cudaFuncSetAttribute(shapeconv_main,
                         cudaFuncAttributeMaxDynamicSharedMemorySize, SMEM_BYTES);

    shapeconv_init<<<(BB * OO + 255) / 256, 256>>>();
    dim3 grid(NT, BB);
    shapeconv_main<<<grid, 256, SMEM_BYTES>>>(x, w);
    shapeconv_finalize<<<(BB * OO + 255) / 256, 256>>>(w, out);
}

// round 3
// speedup vs baseline: 3.0393x; 3.0393x over previous
#include <cuda_runtime.h>
#include <cstdint>

// ShapeConv via warp-level mma.sync TF32 implicit GEMM (target-portable PTX,
// works on plain sm_103 — tcgen05 is unavailable through this toolchain).
// out[b,o] = -2 * ( max_t( conv[b,o,t] - win_norm[b,t] ) - w_norm[o] )

#define BB 32
#define CC 3
#define LL 8192
#define OO 128
#define KW 64
#define WW (LL - KW + 1)   /* 8129 valid windows */
#define NTILE 128          /* time per tile */
#define TPB 2              /* tiles per block */
#define NXB 32             /* gridDim.x = 64 tiles / TPB */
#define KRED 192
#define APITCH 196         /* A smem pitch in words: 4-bank shift/row -> conflict-free */

#define A_OFF   0u
#define XS_OFF  100352u    /* 3*192 tf32 words */
#define SQ_OFF  102656u    /* 192 f32 */
#define WIN_OFF 103424u    /* 128 f32 */
#define RED_OFF 103936u    /* 2*128 f32 */
#define SMEM_BYTES 104960

__device__ unsigned int g_max[BB * OO];

__device__ __forceinline__ unsigned int f2mono(float f) {
    unsigned int u = __float_as_uint(f);
    return (u & 0x80000000u) ? ~u : (u | 0x80000000u);
}
__device__ __forceinline__ float mono2f(unsigned int m) {
    unsigned int u = (m & 0x80000000u) ? (m & 0x7fffffffu) : ~m;
    return __uint_as_float(u);
}
__device__ __forceinline__ uint32_t f2tf32(float v) {
    uint32_t r;
    asm("cvt.rna.tf32.f32 %0, %1;" : "=r"(r) : "f"(v));
    return r;
}
__device__ __forceinline__ void mma_tf32(float* d, const uint32_t* a,
                                         const uint32_t* b) {
    asm volatile(
        "mma.sync.aligned.m16n8k8.row.col.f32.tf32.tf32.f32 "
        "{%0,%1,%2,%3}, {%4,%5,%6,%7}, {%8,%9}, {%0,%1,%2,%3};"
        : "+f"(d[0]), "+f"(d[1]), "+f"(d[2]), "+f"(d[3])
        : "r"(a[0]), "r"(a[1]), "r"(a[2]), "r"(a[3]), "r"(b[0]), "r"(b[1]));
}

__global__ void shapeconv_init() {
    int idx = blockIdx.x * blockDim.x + threadIdx.x;
    if (idx < BB * OO) g_max[idx] = 0u;   // 0 < f2mono(-inf)
}

extern "C" __global__ void __launch_bounds__(256, 2)
shapeconv_mma(const float* __restrict__ xg, const float* __restrict__ wg) {
    extern __shared__ char smem[];
    uint32_t* A_s = (uint32_t*)(smem + A_OFF);     // [128][APITCH] tf32
    uint32_t* xs  = (uint32_t*)(smem + XS_OFF);    // [3][192] tf32
    float*    sq  = (float*)(smem + SQ_OFF);       // [192]
    float*    win = (float*)(smem + WIN_OFF);      // [128]
    float*    red = (float*)(smem + RED_OFF);      // [2][128]

    const int tid  = threadIdx.x;
    const int wid  = tid >> 5;
    const int lane = tid & 31;
    const int b    = blockIdx.y;

    const int m0  = (wid & 3) * 32;    // warp o-base
    const int n0w = (wid >> 2) * 64;   // warp t-base

    // ---- A: weights as tf32, row-major [o][k], pitch 196 ----
    for (int i = tid; i < OO * KRED; i += 256) {
        int o = i / KRED, k = i % KRED;
        A_s[o * APITCH + k] = f2tf32(wg[i]);
    }

    const float* xb = xg + b * CC * LL;
    float vrun = __int_as_float(0xff800000);   // per-o running max (tid<128)
    __syncthreads();

    for (int it = 0; it < TPB; ++it) {
        const int t0 = (blockIdx.x * TPB + it) * NTILE;

        // ---- x slice: tf32 for MMA B, exact fp32 squared sums for norms ----
        for (int j = tid; j < KRED; j += 256) {
            int g = t0 + j;
            float a0 = 0.f, a1 = 0.f, a2 = 0.f;
            if (g < LL) { a0 = xb[g]; a1 = xb[LL + g]; a2 = xb[2 * LL + g]; }
            xs[j] = f2tf32(a0); xs[192 + j] = f2tf32(a1); xs[384 + j] = f2tf32(a2);
            sq[j] = a0 * a0 + a1 * a1 + a2 * a2;
        }
        __syncthreads();

        if (tid < NTILE) {
            float s = 0.f;
            #pragma unroll 16
            for (int k = 0; k < KW; ++k) s += sq[tid + k];
            win[tid] = (t0 + tid < WW) ? 0.5f * s : __int_as_float(0x7f800000);
        }
        __syncthreads();

        // ---- warp-tiled MMA: 32 o x 64 t per warp, K=192 ----
        float acc[2][8][4];
        #pragma unroll
        for (int mi = 0; mi < 2; ++mi)
            #pragma unroll
            for (int nf = 0; nf < 8; ++nf)
                #pragma unroll
                for (int r = 0; r < 4; ++r) acc[mi][nf][r] = 0.f;

        const int off1 = (lane >> 2) + (lane & 3);   // B frag lane pattern

        #pragma unroll 1
        for (int c = 0; c < CC; ++c) {
            const uint32_t* xc = xs + c * 192;
            uint32_t bf[8][2];   // diagonal ring: slot s holds frag s-index == s (mod 8)
            #pragma unroll
            for (int f = 0; f < 8; ++f) {
                int s = n0w + f * 8 + off1;
                bf[f][0] = xc[s]; bf[f][1] = xc[s + 4];
            }
            #pragma unroll
            for (int j = 0; j < 8; ++j) {
                const int rb = (m0 + (lane >> 2)) * APITCH + c * 64 + j * 8 + (lane & 3);
                uint32_t a[2][4];
                #pragma unroll
                for (int mi = 0; mi < 2; ++mi) {
                    a[mi][0] = A_s[rb + (mi * 16) * APITCH];
                    a[mi][1] = A_s[rb + (mi * 16 + 8) * APITCH];
                    a[mi][2] = A_s[rb + (mi * 16) * APITCH + 4];
                    a[mi][3] = A_s[rb + (mi * 16 + 8) * APITCH + 4];
                }
                #pragma unroll
                for (int nf = 0; nf < 8; ++nf) {
                    const int slot = (nf + j) & 7;
                    mma_tf32(acc[0][nf], a[0], bf[slot]);
                    mma_tf32(acc[1][nf], a[1], bf[slot]);
                }
                if (j < 7) {   // refill retired slot with s-index j+8
                    int s = n0w + (j + 8) * 8 + off1;
                    bf[j & 7][0] = xc[s]; bf[j & 7][1] = xc[s + 4];
                }
            }
        }

        // ---- epilogue: feature = D - win[n], per-row max ----
        float mrow[4];
        #pragma unroll
        for (int r = 0; r < 4; ++r) mrow[r] = __int_as_float(0xff800000);
        #pragma unroll
        for (int mi = 0; mi < 2; ++mi)
            #pragma unroll
            for (int nf = 0; nf < 8; ++nf) {
                int ncol = n0w + nf * 8 + 2 * (lane & 3);
                float w0 = win[ncol], w1 = win[ncol + 1];
                float* d = acc[mi][nf];
                mrow[mi * 2]     = fmaxf(mrow[mi * 2],
                                         fmaxf(d[0] - w0, d[1] - w1));
                mrow[mi * 2 + 1] = fmaxf(mrow[mi * 2 + 1],
                                         fmaxf(d[2] - w0, d[3] - w1));
            }
        // reduce over the 4 lanes sharing each row (same lane>>2 group)
        #pragma unroll
        for (int r = 0; r < 4; ++r) {
            mrow[r] = fmaxf(mrow[r], __shfl_xor_sync(0xffffffffu, mrow[r], 1));
            mrow[r] = fmaxf(mrow[r], __shfl_xor_sync(0xffffffffu, mrow[r], 2));
        }
        if ((lane & 3) == 0) {
            #pragma unroll
            for (int r = 0; r < 4; ++r) {
                int row = m0 + (r >> 1) * 16 + (r & 1) * 8 + (lane >> 2);
                red[(wid >> 2) * 128 + row] = mrow[r];
            }
        }
        __syncthreads();
        if (tid < 128) vrun = fmaxf(vrun, fmaxf(red[tid], red[128 + tid]));
        __syncthreads();
    }

    if (tid < 128) atomicMax(&g_max[b * OO + tid], f2mono(vrun));
}

__global__ void shapeconv_finalize(const float* __restrict__ wg,
                                   float* __restrict__ out) {
    int idx = blockIdx.x * blockDim.x + threadIdx.x;
    if (idx >= BB * OO) return;
    int o = idx & (OO - 1);
    const float* wr = wg + o * KRED;
    float s = 0.f;
    #pragma unroll 8
    for (int i = 0; i < KRED; ++i) s += wr[i] * wr[i];
    out[idx] = -2.0f * (mono2f(g_max[idx]) - 0.5f * s);
}

extern "C" void kernel_launch(void* const* d_in, const int* in_sizes, int n_in,
                              void* d_out, int out_size) {
    const float* x = (const float*)d_in[0];
    const float* w = (const float*)d_in[1];
    float* out = (float*)d_out;

    cudaFuncSetAttribute(shapeconv_mma,
                         cudaFuncAttributeMaxDynamicSharedMemorySize, SMEM_BYTES);

    shapeconv_init<<<(BB * OO + 255) / 256, 256>>>();
    dim3 grid(NXB, BB);
    shapeconv_mma<<<grid, 256, SMEM_BYTES>>>(x, w);
    shapeconv_finalize<<<(BB * OO + 255) / 256, 256>>>(w, out);
}

// round 4
// speedup vs baseline: 4.3641x; 1.4359x over previous
#include <cuda_runtime.h>
#include <cuda_bf16.h>
#include <cstdint>

// ShapeConv via warp-level mma.sync bf16 m16n8k16 implicit GEMM.
// out[b,o] = -2 * ( max_t( conv[b,o,t] - win_norm[b,t] ) - w_norm[o] )

#define BB 32
#define CC 3
#define LL 8192
#define OO 128
#define KW 64
#define WW (LL - KW + 1)   /* 8129 valid windows */
#define NTILE 128
#define TPB 2
#define NXB 32
#define KRED 192
#define APW 100            /* A pitch in 32-bit words (96 data + 4 pad) */

#define A_OFF    0u        /* 128*APW words bf16x2 = 51200 B */
#define XS32_OFF 51200u    /* 3*192 f32 */
#define SQ_OFF   53504u    /* 192 f32 */
#define WIN_OFF  54272u    /* 128 f32 */
#define RED_OFF  54784u    /* 2*128 f32 */
#define XE_OFF   55808u    /* 3*96 bf16x2: (x[2i],x[2i+1]) */
#define XO_OFF   56960u    /* 3*96 bf16x2: (x[2i+1],x[2i+2]) */
#define SMEM_BYTES 58112

__device__ unsigned int g_max[BB * OO];

__device__ __forceinline__ unsigned int f2mono(float f) {
    unsigned int u = __float_as_uint(f);
    return (u & 0x80000000u) ? ~u : (u | 0x80000000u);
}
__device__ __forceinline__ float mono2f(unsigned int m) {
    unsigned int u = (m & 0x80000000u) ? (m & 0x7fffffffu) : ~m;
    return __uint_as_float(u);
}
__device__ __forceinline__ uint32_t pack_bf2(float lo, float hi) {
    __nv_bfloat162 h = __float22bfloat162_rn(make_float2(lo, hi));
    return *(uint32_t*)&h;
}
__device__ __forceinline__ void mma_bf16(float* d, const uint32_t* a,
                                         uint32_t b0, uint32_t b1) {
    asm volatile(
        "mma.sync.aligned.m16n8k16.row.col.f32.bf16.bf16.f32 "
        "{%0,%1,%2,%3}, {%4,%5,%6,%7}, {%8,%9}, {%0,%1,%2,%3};"
        : "+f"(d[0]), "+f"(d[1]), "+f"(d[2]), "+f"(d[3])
        : "r"(a[0]), "r"(a[1]), "r"(a[2]), "r"(a[3]), "r"(b0), "r"(b1));
}

__global__ void shapeconv_init() {
    int idx = blockIdx.x * blockDim.x + threadIdx.x;
    if (idx < BB * OO) g_max[idx] = 0u;   // 0 < f2mono(-inf)
}

extern "C" __global__ void __launch_bounds__(256, 2)
shapeconv_mma(const float* __restrict__ xg, const float* __restrict__ wg) {
    extern __shared__ char smem[];
    uint32_t* A_s  = (uint32_t*)(smem + A_OFF);     // [128][APW] bf16x2
    float*    xs32 = (float*)(smem + XS32_OFF);     // [3][192]
    float*    sq   = (float*)(smem + SQ_OFF);
    float*    win  = (float*)(smem + WIN_OFF);
    float*    red  = (float*)(smem + RED_OFF);
    uint32_t* xe   = (uint32_t*)(smem + XE_OFF);    // [3][96]
    uint32_t* xo   = (uint32_t*)(smem + XO_OFF);    // [3][96]

    const int tid  = threadIdx.x;
    const int wid  = tid >> 5;
    const int lane = tid & 31;
    const int b    = blockIdx.y;

    const int m0  = (wid & 3) * 32;    // warp o-base
    const int n0w = (wid >> 2) * 64;   // warp t-base
    const int r4  = lane >> 2;         // 0..7
    const int q4  = lane & 3;          // 0..3

    // ---- A: weights -> packed bf16x2, row-major [o][kpair] ----
    for (int i = tid; i < OO * 96; i += 256) {
        int o = i / 96, kp = i % 96;
        const float* wp = wg + o * KRED + 2 * kp;
        A_s[o * APW + kp] = pack_bf2(wp[0], wp[1]);
    }

    const float* xb = xg + b * CC * LL;
    float vrun = __int_as_float(0xff800000);

    // B-frag addressing: s = n0w + 8u + r4 + 2*q4 (+c*64); parity(s) = r4&1
    const uint32_t* xpar = (r4 & 1) ? xo : xe;
    const int wbase = (n0w + r4 + 2 * q4) >> 1;

    __syncthreads();

    for (int it = 0; it < TPB; ++it) {
        const int t0 = (blockIdx.x * TPB + it) * NTILE;

        // ---- stage exact fp32 slice + squared sums ----
        for (int j = tid; j < KRED; j += 256) {
            int g = t0 + j;
            float a0 = 0.f, a1 = 0.f, a2 = 0.f;
            if (g < LL) { a0 = xb[g]; a1 = xb[LL + g]; a2 = xb[2 * LL + g]; }
            xs32[j] = a0; xs32[192 + j] = a1; xs32[384 + j] = a2;
            sq[j] = a0 * a0 + a1 * a1 + a2 * a2;
        }
        __syncthreads();

        // ---- exact fp32 window half-norms; packed bf16 unfold sources ----
        if (tid < NTILE) {
            float s = 0.f;
            #pragma unroll 16
            for (int k = 0; k < KW; ++k) s += sq[tid + k];
            win[tid] = (t0 + tid < WW) ? 0.5f * s : __int_as_float(0x7f800000);
        }
        for (int i = tid; i < CC * 96; i += 256) {
            int c = i / 96, j = i % 96;
            const float* xc = xs32 + c * 192;
            float v0 = xc[2 * j], v1 = xc[2 * j + 1];
            float v2 = (2 * j + 2 < 192) ? xc[2 * j + 2] : 0.f;
            xe[i] = pack_bf2(v0, v1);
            xo[i] = pack_bf2(v1, v2);
        }
        __syncthreads();

        // ---- MMA mainloop: 32 o x 64 t per warp, K=192, bf16 k16 steps ----
        float acc[2][8][4];
        #pragma unroll
        for (int mi = 0; mi < 2; ++mi)
            #pragma unroll
            for (int nf = 0; nf < 8; ++nf)
                #pragma unroll
                for (int r = 0; r < 4; ++r) acc[mi][nf][r] = 0.f;

        const int arow = (m0 + r4) * APW + q4;

        #pragma unroll
        for (int c = 0; c < CC; ++c) {
            const uint32_t* xp = xpar + c * 96 + wbase;
            uint32_t bb[15];                  // bb[u] covers all (j,nf) pairs
            #pragma unroll
            for (int u = 0; u < 15; ++u) bb[u] = xp[4 * u];

            #pragma unroll
            for (int j = 0; j < 4; ++j) {
                const int coff = c * 32 + j * 8;
                uint32_t a[2][4];
                #pragma unroll
                for (int mi = 0; mi < 2; ++mi) {
                    const int base = arow + mi * 16 * APW + coff;
                    a[mi][0] = A_s[base];
                    a[mi][1] = A_s[base + 8 * APW];
                    a[mi][2] = A_s[base + 4];
                    a[mi][3] = A_s[base + 8 * APW + 4];
                }
                #pragma unroll
                for (int nf = 0; nf < 8; ++nf) {
                    uint32_t b0 = bb[2 * j + nf], b1 = bb[2 * j + nf + 1];
                    mma_bf16(acc[0][nf], a[0], b0, b1);
                    mma_bf16(acc[1][nf], a[1], b0, b1);
                }
            }
        }

        // ---- epilogue: feature = D - win[n], per-row max ----
        float mrow[4];
        #pragma unroll
        for (int r = 0; r < 4; ++r) mrow[r] = __int_as_float(0xff800000);
        #pragma unroll
        for (int mi = 0; mi < 2; ++mi)
            #pragma unroll
            for (int nf = 0; nf < 8; ++nf) {
                int ncol = n0w + nf * 8 + 2 * q4;
                float w0 = win[ncol], w1 = win[ncol + 1];
                float* d = acc[mi][nf];
                mrow[mi * 2]     = fmaxf(mrow[mi * 2],
                                         fmaxf(d[0] - w0, d[1] - w1));
                mrow[mi * 2 + 1] = fmaxf(mrow[mi * 2 + 1],
                                         fmaxf(d[2] - w0, d[3] - w1));
            }
        #pragma unroll
        for (int r = 0; r < 4; ++r) {
            mrow[r] = fmaxf(mrow[r], __shfl_xor_sync(0xffffffffu, mrow[r], 1));
            mrow[r] = fmaxf(mrow[r], __shfl_xor_sync(0xffffffffu, mrow[r], 2));
        }
        if (q4 == 0) {
            #pragma unroll
            for (int r = 0; r < 4; ++r) {
                int row = m0 + (r >> 1) * 16 + (r & 1) * 8 + r4;
                red[(wid >> 2) * 128 + row] = mrow[r];
            }
        }
        __syncthreads();
        if (tid < 128) vrun = fmaxf(vrun, fmaxf(red[tid], red[128 + tid]));
        __syncthreads();
    }

    if (tid < 128) atomicMax(&g_max[b * OO + tid], f2mono(vrun));
}

__global__ void shapeconv_finalize(const float* __restrict__ wg,
                                   float* __restrict__ out) {
    int idx = blockIdx.x * blockDim.x + threadIdx.x;
    if (idx >= BB * OO) return;
    int o = idx & (OO - 1);
    const float* wr = wg + o * KRED;
    float s = 0.f;
    #pragma unroll 8
    for (int i = 0; i < KRED; ++i) s += wr[i] * wr[i];
    out[idx] = -2.0f * (mono2f(g_max[idx]) - 0.5f * s);
}

extern "C" void kernel_launch(void* const* d_in, const int* in_sizes, int n_in,
                              void* d_out, int out_size) {
    const float* x = (const float*)d_in[0];
    const float* w = (const float*)d_in[1];
    float* out = (float*)d_out;

    cudaFuncSetAttribute(shapeconv_mma,
                         cudaFuncAttributeMaxDynamicSharedMemorySize, SMEM_BYTES);

    shapeconv_init<<<(BB * OO + 255) / 256, 256>>>();
    dim3 grid(NXB, BB);
    shapeconv_mma<<<grid, 256, SMEM_BYTES>>>(x, w);
    shapeconv_finalize<<<(BB * OO + 255) / 256, 256>>>(w, out);
}

// round 5
// speedup vs baseline: 4.4041x; 1.0092x over previous
#include <cuda_runtime.h>
#include <cuda_bf16.h>
#include <cstdint>

// ShapeConv via warp-level mma.sync bf16 m16n8k16 implicit GEMM.
// Round-5: persistent-ish blocks (8 tiles each), no init kernel / no atomics,
// register prefetch of next x slice, split half-window norm sums.

#define BB 32
#define CC 3
#define LL 8192
#define OO 128
#define KW 64
#define WW (LL - KW + 1)   /* 8129 valid windows */
#define NTILE 128
#define TPB 8              /* tiles per block */
#define NXB 8              /* gridDim.x ; NXB*TPB*NTILE >= WW */
#define KRED 192
#define APW 100            /* A pitch in 32-bit words (96 data + 4 pad) */

#define A_OFF    0u        /* 128*APW bf16x2 words = 51200 B */
#define XS32_OFF 51200u    /* 3*192 f32 */
#define SQ_OFF   53504u    /* 192 f32 */
#define S_OFF    54272u    /* 160 f32 half-window sums (pad 164) */
#define RED_OFF  54928u    /* 2*128 f32 */
#define XE_OFF   55952u    /* 3*96 bf16x2 */
#define XO_OFF   57104u    /* 3*96 bf16x2 */
#define SMEM_BYTES 58256

__device__ float g_part[BB * NXB * OO];   // partial maxima, plain stores

__device__ __forceinline__ uint32_t pack_bf2(float lo, float hi) {
    __nv_bfloat162 h = __float22bfloat162_rn(make_float2(lo, hi));
    return *(uint32_t*)&h;
}
__device__ __forceinline__ void mma_bf16(float* d, const uint32_t* a,
                                         uint32_t b0, uint32_t b1) {
    asm volatile(
        "mma.sync.aligned.m16n8k16.row.col.f32.bf16.bf16.f32 "
        "{%0,%1,%2,%3}, {%4,%5,%6,%7}, {%8,%9}, {%0,%1,%2,%3};"
        : "+f"(d[0]), "+f"(d[1]), "+f"(d[2]), "+f"(d[3])
        : "r"(a[0]), "r"(a[1]), "r"(a[2]), "r"(a[3]), "r"(b0), "r"(b1));
}

extern "C" __global__ void __launch_bounds__(256, 2)
shapeconv_mma(const float* __restrict__ xg, const float* __restrict__ wg) {
    extern __shared__ char smem[];
    uint32_t* A_s  = (uint32_t*)(smem + A_OFF);     // [128][APW] bf16x2
    float*    xs32 = (float*)(smem + XS32_OFF);     // [3][192]
    float*    sq   = (float*)(smem + SQ_OFF);       // [192]
    float*    S_s  = (float*)(smem + S_OFF);        // [160]
    float*    red  = (float*)(smem + RED_OFF);      // [2][128]
    uint32_t* xe   = (uint32_t*)(smem + XE_OFF);    // [3][96]
    uint32_t* xo   = (uint32_t*)(smem + XO_OFF);    // [3][96]

    const int tid  = threadIdx.x;
    const int wid  = tid >> 5;
    const int lane = tid & 31;
    const int b    = blockIdx.y;
    const int xblk = blockIdx.x;

    const int m0  = (wid & 3) * 32;    // warp o-base
    const int n0w = (wid >> 2) * 64;   // warp t-base
    const int r4  = lane >> 2;
    const int q4  = lane & 3;

    // ---- A: weights -> packed bf16x2 [o][kpair], staged ONCE per block ----
    for (int i = tid; i < OO * 96; i += 256) {
        int o = i / 96, kp = i % 96;
        const float* wp = wg + o * KRED + 2 * kp;
        A_s[o * APW + kp] = pack_bf2(wp[0], wp[1]);
    }

    const float* xb = xg + b * CC * LL;
    float vrun = __int_as_float(0xff800000);

    // B-frag addressing: s = n0w + 8u + r4 + 2*q4 (+c*64); parity(s) = r4&1
    const uint32_t* xpar = (r4 & 1) ? xo : xe;
    const int wbase = (n0w + r4 + 2 * q4) >> 1;
    const int arow  = (m0 + r4) * APW + q4;

    // prefetch tile 0 x slice into regs (thread tid<192 owns position tid)
    float p0 = 0.f, p1 = 0.f, p2 = 0.f;
    {
        int g = xblk * TPB * NTILE + tid;
        if (tid < KRED && g < LL) { p0 = xb[g]; p1 = xb[LL + g]; p2 = xb[2 * LL + g]; }
    }
    __syncthreads();

    #pragma unroll 1
    for (int it = 0; it < TPB; ++it) {
        const int t0 = (xblk * TPB + it) * NTILE;

        // ---- phase A: spill prefetched regs to smem + squared sums ----
        if (tid < KRED) {
            xs32[tid] = p0; xs32[192 + tid] = p1; xs32[384 + tid] = p2;
            sq[tid] = p0 * p0 + p1 * p1 + p2 * p2;
        }
        __syncthreads();

        // ---- phase B: pack bf16 unfold sources + half-window sums ----
        for (int i = tid; i < CC * 96; i += 256) {
            int c = i / 96, j = i % 96;
            const float* xc = xs32 + c * 192;
            float v0 = xc[2 * j], v1 = xc[2 * j + 1];
            float v2 = (2 * j + 2 < 192) ? xc[2 * j + 2] : 0.f;
            xe[i] = pack_bf2(v0, v1);
            xo[i] = pack_bf2(v1, v2);
        }
        if (tid < 160) {
            float s = 0.f;
            #pragma unroll 8
            for (int k = 0; k < 32; ++k) s += sq[tid + k];
            S_s[tid] = s;
        }
        __syncthreads();

        // ---- prefetch next tile (latency hidden behind MMA) ----
        p0 = p1 = p2 = 0.f;
        if (it + 1 < TPB && tid < KRED) {
            int g = t0 + NTILE + tid;
            if (g < LL) { p0 = xb[g]; p1 = xb[LL + g]; p2 = xb[2 * LL + g]; }
        }

        // ---- MMA mainloop: 32 o x 64 t per warp, K=192 ----
        float acc[2][8][4];
        #pragma unroll
        for (int mi = 0; mi < 2; ++mi)
            #pragma unroll
            for (int nf = 0; nf < 8; ++nf)
                #pragma unroll
                for (int r = 0; r < 4; ++r) acc[mi][nf][r] = 0.f;

        #pragma unroll
        for (int c = 0; c < CC; ++c) {
            const uint32_t* xp = xpar + c * 96 + wbase;
            uint32_t bb[15];
            #pragma unroll
            for (int u = 0; u < 15; ++u) bb[u] = xp[4 * u];

            #pragma unroll
            for (int j = 0; j < 4; ++j) {
                const int coff = c * 32 + j * 8;
                uint32_t a[2][4];
                #pragma unroll
                for (int mi = 0; mi < 2; ++mi) {
                    const int base = arow + mi * 16 * APW + coff;
                    a[mi][0] = A_s[base];
                    a[mi][1] = A_s[base + 8 * APW];
                    a[mi][2] = A_s[base + 4];
                    a[mi][3] = A_s[base + 8 * APW + 4];
                }
                #pragma unroll
                for (int nf = 0; nf < 8; ++nf) {
                    uint32_t b0 = bb[2 * j + nf], b1 = bb[2 * j + nf + 1];
                    mma_bf16(acc[0][nf], a[0], b0, b1);
                    mma_bf16(acc[1][nf], a[1], b0, b1);
                }
            }
        }

        // ---- epilogue: feature = D - (S[n]+S[n+32]), masked, per-row max ----
        float mrow[4];
        #pragma unroll
        for (int r = 0; r < 4; ++r) mrow[r] = __int_as_float(0xff800000);
        #pragma unroll
        for (int mi = 0; mi < 2; ++mi)
            #pragma unroll
            for (int nf = 0; nf < 8; ++nf) {
                int ncol = n0w + nf * 8 + 2 * q4;
                float w0 = 0.5f * (S_s[ncol] + S_s[ncol + 32]);
                float w1 = 0.5f * (S_s[ncol + 1] + S_s[ncol + 33]);
                if (t0 + ncol >= WW)     w0 = __int_as_float(0x7f800000);
                if (t0 + ncol + 1 >= WW) w1 = __int_as_float(0x7f800000);
                float* d = acc[mi][nf];
                mrow[mi * 2]     = fmaxf(mrow[mi * 2],
                                         fmaxf(d[0] - w0, d[1] - w1));
                mrow[mi * 2 + 1] = fmaxf(mrow[mi * 2 + 1],
                                         fmaxf(d[2] - w0, d[3] - w1));
            }
        #pragma unroll
        for (int r = 0; r < 4; ++r) {
            mrow[r] = fmaxf(mrow[r], __shfl_xor_sync(0xffffffffu, mrow[r], 1));
            mrow[r] = fmaxf(mrow[r], __shfl_xor_sync(0xffffffffu, mrow[r], 2));
        }
        if (q4 == 0) {
            #pragma unroll
            for (int r = 0; r < 4; ++r) {
                int row = m0 + (r >> 1) * 16 + (r & 1) * 8 + r4;
                red[(wid >> 2) * 128 + row] = mrow[r];
            }
        }
        __syncthreads();
        if (tid < 128) vrun = fmaxf(vrun, fmaxf(red[tid], red[128 + tid]));
        // no extra sync: red is next written after two syncs (phases A/B)
    }

    if (tid < 128) g_part[(b * NXB + xblk) * OO + tid] = vrun;
}

__global__ void shapeconv_finalize(const float* __restrict__ wg,
                                   float* __restrict__ out) {
    int idx = blockIdx.x * blockDim.x + threadIdx.x;
    if (idx >= BB * OO) return;
    int o = idx & (OO - 1);
    int b = idx >> 7;
    const float* wr = wg + o * KRED;
    float s = 0.f;
    #pragma unroll 8
    for (int i = 0; i < KRED; ++i) s += wr[i] * wr[i];
    float v = __int_as_float(0xff800000);
    #pragma unroll
    for (int p = 0; p < NXB; ++p)
        v = fmaxf(v, g_part[(b * NXB + p) * OO + o]);
    out[idx] = -2.0f * (v - 0.5f * s);
}

extern "C" void kernel_launch(void* const* d_in, const int* in_sizes, int n_in,
                              void* d_out, int out_size) {
    const float* x = (const float*)d_in[0];
    const float* w = (const float*)d_in[1];
    float* out = (float*)d_out;

    cudaFuncSetAttribute(shapeconv_mma,
                         cudaFuncAttributeMaxDynamicSharedMemorySize, SMEM_BYTES);

    dim3 grid(NXB, BB);
    shapeconv_mma<<<grid, 256, SMEM_BYTES>>>(x, w);
    shapeconv_finalize<<<(BB * OO + 255) / 256, 256>>>(w, out);
}